// round 2
// baseline (speedup 1.0000x reference)
#include <cuda_runtime.h>
#include <cuda_bf16.h>
#include <cstdint>

#define T_STEPS 512
#define BATCH   8
#define HID     512
#define VOCAB   32000

// ---------------- device-global scratch (rewritten every replay) ------------
__device__ float    g_inp[T_STEPS * BATCH * HID];   // 8 MB: emb[x]+pos
__device__ int      g_any1[BATCH];                  // layer-1 spiked for batch b
__device__ int      g_dirtyB[BATCH];                // batch went through fallback
__device__ int      g_mode23;                       // 1 -> A-masks valid
__device__ unsigned g_any3A[T_STEPS];               // batch-independent spk3-any
__device__ unsigned g_maskA[T_STEPS * 16];
__device__ unsigned g_any3B[T_STEPS * BATCH];       // per-(t,b) fallback spk3
__device__ unsigned g_maskB[T_STEPS * BATCH * 16];

__device__ __forceinline__ float clip01(float b) { return fminf(fmaxf(b, 0.f), 1.f); }

// ===========================================================================
// K1a: inp[t,b,h] = emb[x[t,b]][h] + pos[t][h]
// ===========================================================================
__global__ void __launch_bounds__(256) k1a_inp(
    const int* __restrict__ x,
    const float* __restrict__ emb,
    const float* __restrict__ pos)
{
    const int total = T_STEPS * BATCH * HID;
    for (int i = blockIdx.x * blockDim.x + threadIdx.x; i < total;
         i += gridDim.x * blockDim.x) {
        const int h = i & (HID - 1);
        const int b = (i >> 9) & (BATCH - 1);
        const int t = i >> 12;
        const int xv = x[t * BATCH + b];
        g_inp[i] = emb[(size_t)xv * HID + h] + pos[t * HID + h];
    }
}

// ===========================================================================
// K1b: blocks 0..7 = exact reset-free layer-1 scan for batch b (any m_t > 1?)
//      block 8     = layers 2/3 closed-form bound; exact const-input sim if risky
// ===========================================================================
__global__ void __launch_bounds__(512) k1b_detect(
    const float* __restrict__ beta1,
    const float* __restrict__ beta2,
    const float* __restrict__ beta3,
    const float* __restrict__ b2,
    const float* __restrict__ W3,
    const float* __restrict__ b3)
{
    const int tid = threadIdx.x;

    if (blockIdx.x < BATCH) {
        const int b = blockIdx.x;
        const int h = tid;
        const float bt = clip01(beta1[h]);
        const float* ip = g_inp + b * HID + h;
        float m = 0.f;
        int any = 0;
#pragma unroll 8
        for (int t = 0; t < T_STEPS; t++) {
            m = bt * m + ip[(size_t)t * (BATCH * HID)];
            any |= (m > 1.0f);
        }
        int r = __syncthreads_or(any);
        if (tid == 0) g_any1[b] = r;
        return;
    }

    // ---- block 8: layers 2/3, batch-independent (applies when spk1 == 0) ----
    // LIF2 input = relu(b2) constant; reset-free max is c*(1-beta^T)/(1-beta).
    float lim = 0.f;
    {
        const int h = tid;
        float be2 = clip01(beta2[h]);
        float c2  = fmaxf(b2[h], 0.f);
        float g2  = (be2 >= 1.f) ? (float)T_STEPS
                                 : (1.f - powf(be2, (float)T_STEPS)) / (1.f - be2);
        float be3 = clip01(beta3[h]);
        float c3  = fmaxf(b3[h], 0.f);
        float g3  = (be3 >= 1.f) ? (float)T_STEPS
                                 : (1.f - powf(be3, (float)T_STEPS)) / (1.f - be3);
        lim = fmaxf(c2 * g2, c3 * g3);
    }
    int risky = __syncthreads_or(lim >= 0.999f);
    if (tid == 0) g_mode23 = risky;
    if (!risky || tid >= 32) return;

    // exact sequential sim of layers 2/3 with constant LIF2 input relu(b2)
    __shared__ float spkSh[HID];
    const int lane = tid;
    float m2[16], m3[16], s2[16], s3[16];
    float bb2[16], bb3[16], rb2[16], rb3[16], b3raw[16];
#pragma unroll
    for (int k = 0; k < 16; k++) {
        int h = lane + 32 * k;
        m2[k] = m3[k] = s2[k] = s3[k] = 0.f;
        bb2[k] = clip01(beta2[h]); bb3[k] = clip01(beta3[h]);
        rb2[k] = fmaxf(b2[h], 0.f);
        b3raw[k] = b3[h];
        rb3[k] = fmaxf(b3raw[k], 0.f);
    }
    for (int t = 0; t < T_STEPS; t++) {
        bool a = false;
#pragma unroll
        for (int k = 0; k < 16; k++) {
            m2[k] = bb2[k] * m2[k] + rb2[k] - s2[k];
            s2[k] = (m2[k] > 1.f) ? 1.f : 0.f;
            a = a || (s2[k] > 0.f);
        }
        unsigned a2 = __ballot_sync(0xffffffffu, a);
        float h3[16];
        if (a2) {
#pragma unroll
            for (int k = 0; k < 16; k++) spkSh[lane + 32 * k] = s2[k];
            __syncwarp();
#pragma unroll
            for (int k = 0; k < 16; k++) {
                int h = lane + 32 * k;
                float acc = b3raw[k];
                for (int j = 0; j < HID; j++)
                    if (spkSh[j] != 0.f) acc += W3[(size_t)h * HID + j];
                h3[k] = fmaxf(acc, 0.f);
            }
            __syncwarp();
        } else {
#pragma unroll
            for (int k = 0; k < 16; k++) h3[k] = rb3[k];
        }
        bool a3f = false;
#pragma unroll
        for (int k = 0; k < 16; k++) {
            m3[k] = bb3[k] * m3[k] + h3[k] - s3[k];
            s3[k] = (m3[k] > 1.f) ? 1.f : 0.f;
            a3f = a3f || (s3[k] > 0.f);
        }
        unsigned a3 = __ballot_sync(0xffffffffu, a3f);
        if (lane == 0) g_any3A[t] = a3 ? 1u : 0u;
        if (a3) {
#pragma unroll
            for (int k = 0; k < 16; k++) {
                unsigned mk = __ballot_sync(0xffffffffu, s3[k] != 0.f);
                if (lane == 0) g_maskA[t * 16 + k] = mk;
            }
        }
    }
}

// ===========================================================================
// K2: exact full 3-layer resim for batches where layer-1 spiked (normally no-op)
// ===========================================================================
__global__ void __launch_bounds__(32) k2_fallback(
    const float* __restrict__ beta1,
    const float* __restrict__ beta2,
    const float* __restrict__ beta3,
    const float* __restrict__ W2,
    const float* __restrict__ b2,
    const float* __restrict__ W3,
    const float* __restrict__ b3)
{
    const int b = blockIdx.x;
    const int lane = threadIdx.x;
    const int any = g_any1[b];
    if (lane == 0) g_dirtyB[b] = any;
    if (!any) return;

    __shared__ float spkSh[HID];
    float m1[16], m2[16], m3[16], s1[16], s2[16], s3[16];
    float bt1[16], bt2[16], bt3[16], b2r[16], b3r[16];
#pragma unroll
    for (int k = 0; k < 16; k++) {
        int h = lane + 32 * k;
        m1[k] = m2[k] = m3[k] = 0.f;
        s1[k] = s2[k] = s3[k] = 0.f;
        bt1[k] = clip01(beta1[h]); bt2[k] = clip01(beta2[h]); bt3[k] = clip01(beta3[h]);
        b2r[k] = b2[h]; b3r[k] = b3[h];
    }
    for (int t = 0; t < T_STEPS; t++) {
        const float* ip = g_inp + (size_t)t * (BATCH * HID) + b * HID;
        bool a = false;
#pragma unroll
        for (int k = 0; k < 16; k++) {
            int h = lane + 32 * k;
            m1[k] = bt1[k] * m1[k] + ip[h] - s1[k];
            s1[k] = (m1[k] > 1.f) ? 1.f : 0.f;
            a = a || (s1[k] > 0.f);
        }
        unsigned a1 = __ballot_sync(0xffffffffu, a);
        float h2[16];
        if (a1) {
#pragma unroll
            for (int k = 0; k < 16; k++) spkSh[lane + 32 * k] = s1[k];
            __syncwarp();
#pragma unroll
            for (int k = 0; k < 16; k++) {
                int h = lane + 32 * k;
                float acc = b2r[k];
                for (int j = 0; j < HID; j++)
                    if (spkSh[j] != 0.f) acc += W2[(size_t)h * HID + j];
                h2[k] = fmaxf(acc, 0.f);
            }
            __syncwarp();
        } else {
#pragma unroll
            for (int k = 0; k < 16; k++) h2[k] = fmaxf(b2r[k], 0.f);
        }
        a = false;
#pragma unroll
        for (int k = 0; k < 16; k++) {
            m2[k] = bt2[k] * m2[k] + h2[k] - s2[k];
            s2[k] = (m2[k] > 1.f) ? 1.f : 0.f;
            a = a || (s2[k] > 0.f);
        }
        unsigned a2 = __ballot_sync(0xffffffffu, a);
        float h3[16];
        if (a2) {
#pragma unroll
            for (int k = 0; k < 16; k++) spkSh[lane + 32 * k] = s2[k];
            __syncwarp();
#pragma unroll
            for (int k = 0; k < 16; k++) {
                int h = lane + 32 * k;
                float acc = b3r[k];
                for (int j = 0; j < HID; j++)
                    if (spkSh[j] != 0.f) acc += W3[(size_t)h * HID + j];
                h3[k] = fmaxf(acc, 0.f);
            }
            __syncwarp();
        } else {
#pragma unroll
            for (int k = 0; k < 16; k++) h3[k] = fmaxf(b3r[k], 0.f);
        }
        a = false;
#pragma unroll
        for (int k = 0; k < 16; k++) {
            m3[k] = bt3[k] * m3[k] + h3[k] - s3[k];
            s3[k] = (m3[k] > 1.f) ? 1.f : 0.f;
            a = a || (s3[k] > 0.f);
        }
        unsigned a3 = __ballot_sync(0xffffffffu, a);
        int row = t * BATCH + b;
        if (lane == 0) g_any3B[row] = a3 ? 1u : 0u;
        if (a3) {
#pragma unroll
            for (int k = 0; k < 16; k++) {
                unsigned mk = __ballot_sync(0xffffffffu, s3[k] != 0.f);
                if (lane == 0) g_maskB[row * 16 + k] = mk;
            }
        }
    }
}

// ===========================================================================
// K3: logits. Fast path: out[row] = bout (registers -> streaming float4 stores).
//     Slow path (row flagged): out[v] = bout[v] + sum over set h of Wout[v][h].
// grid = 16 vocab chunks (2000 floats) x 128 row groups (32 rows) = 2048 CTAs
// ===========================================================================
__device__ __forceinline__ float mask_sum(const unsigned* __restrict__ mp,
                                          const float* __restrict__ wrow)
{
    float a = 0.f;
#pragma unroll
    for (int k = 0; k < 16; k++) {
        unsigned m = mp[k];
        while (m) {
            int j = __ffs(m) - 1;
            m &= m - 1;
            a += wrow[32 * k + j];
        }
    }
    return a;
}

__global__ void __launch_bounds__(256) k3_logits(
    const float* __restrict__ Wout,
    const float* __restrict__ bout,
    float*       __restrict__ out)
{
    const int tid   = threadIdx.x;
    const int c     = blockIdx.x & 15;        // vocab chunk
    const int g     = blockIdx.x >> 4;        // row group
    const int vbase = c * 2000;
    const bool has2 = (tid + 256) < 500;      // 500 float4 per chunk

    float4 r0 = *reinterpret_cast<const float4*>(bout + vbase + tid * 4);
    float4 r1 = make_float4(0.f, 0.f, 0.f, 0.f);
    if (has2) r1 = *reinterpret_cast<const float4*>(bout + vbase + (tid + 256) * 4);

    const int mode23 = g_mode23;
    int dirty[BATCH];
#pragma unroll
    for (int b = 0; b < BATCH; b++) dirty[b] = g_dirtyB[b];

    const int row0 = g * 32;
    for (int r = 0; r < 32; r++) {
        const int row = row0 + r;
        const int t = row >> 3;
        const int b = row & 7;
        unsigned fl = 0;
        const unsigned* mp = nullptr;
        if (dirty[b]) {
            fl = g_any3B[row];
            mp = &g_maskB[row * 16];
        } else if (mode23) {
            fl = g_any3A[t];
            mp = &g_maskA[t * 16];
        }
        float* op = out + (size_t)row * VOCAB + vbase;
        if (!fl) {
            __stcs(reinterpret_cast<float4*>(op + tid * 4), r0);
            if (has2)
                __stcs(reinterpret_cast<float4*>(op + (tid + 256) * 4), r1);
        } else {
            // exact sparse gather path
            unsigned mloc[16];
#pragma unroll
            for (int k = 0; k < 16; k++) mloc[k] = mp[k];
            {
                float4 o = r0;
                int v0 = vbase + tid * 4;
                o.x += mask_sum(mloc, Wout + (size_t)(v0 + 0) * HID);
                o.y += mask_sum(mloc, Wout + (size_t)(v0 + 1) * HID);
                o.z += mask_sum(mloc, Wout + (size_t)(v0 + 2) * HID);
                o.w += mask_sum(mloc, Wout + (size_t)(v0 + 3) * HID);
                __stcs(reinterpret_cast<float4*>(op + tid * 4), o);
            }
            if (has2) {
                float4 o = r1;
                int v0 = vbase + (tid + 256) * 4;
                o.x += mask_sum(mloc, Wout + (size_t)(v0 + 0) * HID);
                o.y += mask_sum(mloc, Wout + (size_t)(v0 + 1) * HID);
                o.z += mask_sum(mloc, Wout + (size_t)(v0 + 2) * HID);
                o.w += mask_sum(mloc, Wout + (size_t)(v0 + 3) * HID);
                __stcs(reinterpret_cast<float4*>(op + (tid + 256) * 4), o);
            }
        }
    }
}

// ===========================================================================
extern "C" void kernel_launch(void* const* d_in, const int* in_sizes, int n_in,
                              void* d_out, int out_size)
{
    const int*   x     = (const int*)  d_in[0];
    const float* emb   = (const float*)d_in[1];
    const float* pos   = (const float*)d_in[2];
    const float* beta1 = (const float*)d_in[3];
    const float* beta2 = (const float*)d_in[4];
    const float* beta3 = (const float*)d_in[5];
    const float* W2    = (const float*)d_in[6];
    const float* b2    = (const float*)d_in[7];
    const float* W3    = (const float*)d_in[8];
    const float* b3    = (const float*)d_in[9];
    const float* Wout  = (const float*)d_in[10];
    const float* bout  = (const float*)d_in[11];
    float* out = (float*)d_out;

    k1a_inp<<<2048, 256>>>(x, emb, pos);
    k1b_detect<<<BATCH + 1, 512>>>(beta1, beta2, beta3, b2, W3, b3);
    k2_fallback<<<BATCH, 32>>>(beta1, beta2, beta3, W2, b2, W3, b3);
    k3_logits<<<2048, 256>>>(Wout, bout, out);
}

// round 3
// speedup vs baseline: 1.0929x; 1.0929x over previous
#include <cuda_runtime.h>
#include <cuda_bf16.h>
#include <cstdint>

#define T_STEPS 512
#define BATCH   8
#define HID     512
#define VOCAB   32000
#define CHUNK   32                      // t-steps per scan chunk
#define NCHUNK  (T_STEPS / CHUNK)       // 16

// ---------------- device-global scratch (rewritten every replay) ------------
__device__ float    g_loc[NCHUNK * BATCH * HID * CHUNK]; // 8 MB, [(c,b,h)][i]
__device__ float    g_carry[NCHUNK * BATCH * HID];       // chunk-final locals
__device__ int      g_any1[BATCH];                  // layer-1 may spike (batch b)
__device__ int      g_dirtyB[BATCH];                // batch went through fallback
__device__ int      g_mode23;                       // 1 -> A-masks valid
__device__ unsigned g_any3A[T_STEPS];               // batch-independent spk3-any
__device__ unsigned g_maskA[T_STEPS * 16];
__device__ unsigned g_any3B[T_STEPS * BATCH];       // per-(t,b) fallback spk3
__device__ unsigned g_maskB[T_STEPS * BATCH * 16];

__device__ __forceinline__ float clip01(float b) { return fminf(fmaxf(b, 0.f), 1.f); }

// ===========================================================================
// K1A: per-chunk reset-free layer-1 local scan.
//   grid 128 = chunk c (bx>>3) x batch b (bx&7), 512 threads (h).
//   local_t = sum_{i=cL..t} beta^(t-i) u_i   (u = emb[x]+pos, gathered inline)
// ===========================================================================
__global__ void __launch_bounds__(512) k1A_scan(
    const int*   __restrict__ x,
    const float* __restrict__ emb,
    const float* __restrict__ pos,
    const float* __restrict__ beta1)
{
    const int c = blockIdx.x >> 3;
    const int b = blockIdx.x & 7;
    const int h = threadIdx.x;
    const int t0 = c * CHUNK;

    __shared__ unsigned xoff[CHUNK];
    if (h < CHUNK) xoff[h] = (unsigned)x[(t0 + h) * BATCH + b] * (unsigned)HID;
    if (blockIdx.x == 0 && h < BATCH) g_any1[h] = 0;   // zero flags for pass B
    __syncthreads();

    const float bt = clip01(beta1[h]);
    float loc = 0.f;
    float* lp = g_loc + ((size_t)(c * BATCH + b) * HID + h) * CHUNK;

#pragma unroll
    for (int i = 0; i < CHUNK; i++) {
        const float e = emb[(size_t)xoff[i] + h];
        const float p = pos[(size_t)(t0 + i) * HID + h];
        loc = bt * loc + (e + p);
        lp[i] = loc;
    }
    g_carry[(size_t)(c * BATCH + b) * HID + h] = loc;
}

// ===========================================================================
// K1B: combine + spike check.
//   blocks 0..127: (c,b); thread h: M_c from carries, then test 32 steps.
//   block 128    : layers 2/3 closed-form bound (+ exact sim if risky).
// Decision threshold 0.98 (conservative): anything near 1.0 goes to K2 exact.
// ===========================================================================
__global__ void __launch_bounds__(512) k1B_combine(
    const float* __restrict__ beta1,
    const float* __restrict__ beta2,
    const float* __restrict__ beta3,
    const float* __restrict__ b2,
    const float* __restrict__ W3,
    const float* __restrict__ b3)
{
    const int tid = threadIdx.x;

    if (blockIdx.x < NCHUNK * BATCH) {
        const int c = blockIdx.x >> 3;
        const int b = blockIdx.x & 7;
        const int h = tid;

        const float bt = clip01(beta1[h]);
        float btL = bt;                       // beta^32 via 5 squarings
        btL = btL * btL; btL = btL * btL; btL = btL * btL;
        btL = btL * btL; btL = btL * btL;

        float M = 0.f;                        // m at step c*CHUNK - 1
        for (int cp = 0; cp < c; cp++)
            M = btL * M + g_carry[(size_t)(cp * BATCH + b) * HID + h];

        const float* lp = g_loc + ((size_t)(c * BATCH + b) * HID + h) * CHUNK;
        bool any = false;
        float s = bt;                         // beta^(i+1)
#pragma unroll
        for (int i = 0; i < CHUNK; i++) {
            any = any || (s * M + lp[i] > 0.98f);
            s *= bt;
        }
        int r = __syncthreads_or(any);
        if (tid == 0 && r) atomicOr(&g_any1[b], 1);
        return;
    }

    // ---- block 128: layers 2/3, batch-independent (valid when spk1 == 0) ----
    float lim = 0.f;
    {
        const int h = tid;
        float be2 = clip01(beta2[h]);
        float c2  = fmaxf(b2[h], 0.f);
        float g2  = (be2 >= 1.f) ? (float)T_STEPS
                                 : (1.f - powf(be2, (float)T_STEPS)) / (1.f - be2);
        float be3 = clip01(beta3[h]);
        float c3  = fmaxf(b3[h], 0.f);
        float g3  = (be3 >= 1.f) ? (float)T_STEPS
                                 : (1.f - powf(be3, (float)T_STEPS)) / (1.f - be3);
        lim = fmaxf(c2 * g2, c3 * g3);
    }
    int risky = __syncthreads_or(lim >= 0.98f);
    if (tid == 0) g_mode23 = risky;
    if (!risky || tid >= 32) return;

    // exact sequential sim of layers 2/3 with constant LIF2 input relu(b2)
    __shared__ float spkSh[HID];
    const int lane = tid;
    float m2[16], m3[16], s2[16], s3[16];
    float bb2[16], bb3[16], rb2[16], rb3[16], b3raw[16];
#pragma unroll
    for (int k = 0; k < 16; k++) {
        int h = lane + 32 * k;
        m2[k] = m3[k] = s2[k] = s3[k] = 0.f;
        bb2[k] = clip01(beta2[h]); bb3[k] = clip01(beta3[h]);
        rb2[k] = fmaxf(b2[h], 0.f);
        b3raw[k] = b3[h];
        rb3[k] = fmaxf(b3raw[k], 0.f);
    }
    for (int t = 0; t < T_STEPS; t++) {
        bool a = false;
#pragma unroll
        for (int k = 0; k < 16; k++) {
            m2[k] = bb2[k] * m2[k] + rb2[k] - s2[k];
            s2[k] = (m2[k] > 1.f) ? 1.f : 0.f;
            a = a || (s2[k] > 0.f);
        }
        unsigned a2 = __ballot_sync(0xffffffffu, a);
        float h3[16];
        if (a2) {
#pragma unroll
            for (int k = 0; k < 16; k++) spkSh[lane + 32 * k] = s2[k];
            __syncwarp();
#pragma unroll
            for (int k = 0; k < 16; k++) {
                int h = lane + 32 * k;
                float acc = b3raw[k];
                for (int j = 0; j < HID; j++)
                    if (spkSh[j] != 0.f) acc += W3[(size_t)h * HID + j];
                h3[k] = fmaxf(acc, 0.f);
            }
            __syncwarp();
        } else {
#pragma unroll
            for (int k = 0; k < 16; k++) h3[k] = rb3[k];
        }
        bool a3f = false;
#pragma unroll
        for (int k = 0; k < 16; k++) {
            m3[k] = bb3[k] * m3[k] + h3[k] - s3[k];
            s3[k] = (m3[k] > 1.f) ? 1.f : 0.f;
            a3f = a3f || (s3[k] > 0.f);
        }
        unsigned a3 = __ballot_sync(0xffffffffu, a3f);
        if (lane == 0) g_any3A[t] = a3 ? 1u : 0u;
        if (a3) {
#pragma unroll
            for (int k = 0; k < 16; k++) {
                unsigned mk = __ballot_sync(0xffffffffu, s3[k] != 0.f);
                if (lane == 0) g_maskA[t * 16 + k] = mk;
            }
        }
    }
}

// ===========================================================================
// K2: exact full 3-layer sequential resim for flagged batches (normally no-op)
// ===========================================================================
__global__ void __launch_bounds__(32) k2_fallback(
    const int*   __restrict__ x,
    const float* __restrict__ emb,
    const float* __restrict__ pos,
    const float* __restrict__ beta1,
    const float* __restrict__ beta2,
    const float* __restrict__ beta3,
    const float* __restrict__ W2,
    const float* __restrict__ b2,
    const float* __restrict__ W3,
    const float* __restrict__ b3)
{
    const int b = blockIdx.x;
    const int lane = threadIdx.x;
    const int any = g_any1[b];
    if (lane == 0) g_dirtyB[b] = any;
    if (!any) return;

    __shared__ float spkSh[HID];
    float m1[16], m2[16], m3[16], s1[16], s2[16], s3[16];
    float bt1[16], bt2[16], bt3[16], b2r[16], b3r[16];
#pragma unroll
    for (int k = 0; k < 16; k++) {
        int h = lane + 32 * k;
        m1[k] = m2[k] = m3[k] = 0.f;
        s1[k] = s2[k] = s3[k] = 0.f;
        bt1[k] = clip01(beta1[h]); bt2[k] = clip01(beta2[h]); bt3[k] = clip01(beta3[h]);
        b2r[k] = b2[h]; b3r[k] = b3[h];
    }
    for (int t = 0; t < T_STEPS; t++) {
        const int xv = x[t * BATCH + b];
        const float* ep = emb + (size_t)xv * HID;
        const float* pp = pos + (size_t)t * HID;
        bool a = false;
#pragma unroll
        for (int k = 0; k < 16; k++) {
            int h = lane + 32 * k;
            m1[k] = bt1[k] * m1[k] + (ep[h] + pp[h]) - s1[k];
            s1[k] = (m1[k] > 1.f) ? 1.f : 0.f;
            a = a || (s1[k] > 0.f);
        }
        unsigned a1 = __ballot_sync(0xffffffffu, a);
        float h2[16];
        if (a1) {
#pragma unroll
            for (int k = 0; k < 16; k++) spkSh[lane + 32 * k] = s1[k];
            __syncwarp();
#pragma unroll
            for (int k = 0; k < 16; k++) {
                int h = lane + 32 * k;
                float acc = b2r[k];
                for (int j = 0; j < HID; j++)
                    if (spkSh[j] != 0.f) acc += W2[(size_t)h * HID + j];
                h2[k] = fmaxf(acc, 0.f);
            }
            __syncwarp();
        } else {
#pragma unroll
            for (int k = 0; k < 16; k++) h2[k] = fmaxf(b2r[k], 0.f);
        }
        a = false;
#pragma unroll
        for (int k = 0; k < 16; k++) {
            m2[k] = bt2[k] * m2[k] + h2[k] - s2[k];
            s2[k] = (m2[k] > 1.f) ? 1.f : 0.f;
            a = a || (s2[k] > 0.f);
        }
        unsigned a2 = __ballot_sync(0xffffffffu, a);
        float h3[16];
        if (a2) {
#pragma unroll
            for (int k = 0; k < 16; k++) spkSh[lane + 32 * k] = s2[k];
            __syncwarp();
#pragma unroll
            for (int k = 0; k < 16; k++) {
                int h = lane + 32 * k;
                float acc = b3r[k];
                for (int j = 0; j < HID; j++)
                    if (spkSh[j] != 0.f) acc += W3[(size_t)h * HID + j];
                h3[k] = fmaxf(acc, 0.f);
            }
            __syncwarp();
        } else {
#pragma unroll
            for (int k = 0; k < 16; k++) h3[k] = fmaxf(b3r[k], 0.f);
        }
        a = false;
#pragma unroll
        for (int k = 0; k < 16; k++) {
            m3[k] = bt3[k] * m3[k] + h3[k] - s3[k];
            s3[k] = (m3[k] > 1.f) ? 1.f : 0.f;
            a = a || (s3[k] > 0.f);
        }
        unsigned a3 = __ballot_sync(0xffffffffu, a);
        int row = t * BATCH + b;
        if (lane == 0) g_any3B[row] = a3 ? 1u : 0u;
        if (a3) {
#pragma unroll
            for (int k = 0; k < 16; k++) {
                unsigned mk = __ballot_sync(0xffffffffu, s3[k] != 0.f);
                if (lane == 0) g_maskB[row * 16 + k] = mk;
            }
        }
    }
}

// ===========================================================================
// K3: logits. Fast path: out[row] = bout (registers -> streaming float4 stores).
//     Slow path (row flagged): out[v] = bout[v] + sum over set h of Wout[v][h].
// ===========================================================================
__device__ __forceinline__ float mask_sum(const unsigned* __restrict__ mp,
                                          const float* __restrict__ wrow)
{
    float a = 0.f;
#pragma unroll
    for (int k = 0; k < 16; k++) {
        unsigned m = mp[k];
        while (m) {
            int j = __ffs(m) - 1;
            m &= m - 1;
            a += wrow[32 * k + j];
        }
    }
    return a;
}

__global__ void __launch_bounds__(256) k3_logits(
    const float* __restrict__ Wout,
    const float* __restrict__ bout,
    float*       __restrict__ out)
{
    const int tid   = threadIdx.x;
    const int c     = blockIdx.x & 15;        // vocab chunk
    const int g     = blockIdx.x >> 4;        // row group
    const int vbase = c * 2000;
    const bool has2 = (tid + 256) < 500;      // 500 float4 per chunk

    float4 r0 = *reinterpret_cast<const float4*>(bout + vbase + tid * 4);
    float4 r1 = make_float4(0.f, 0.f, 0.f, 0.f);
    if (has2) r1 = *reinterpret_cast<const float4*>(bout + vbase + (tid + 256) * 4);

    const int mode23 = g_mode23;
    int dirty[BATCH];
#pragma unroll
    for (int b = 0; b < BATCH; b++) dirty[b] = g_dirtyB[b];

    const int row0 = g * 32;
    for (int r = 0; r < 32; r++) {
        const int row = row0 + r;
        const int t = row >> 3;
        const int b = row & 7;
        unsigned fl = 0;
        const unsigned* mp = nullptr;
        if (dirty[b]) {
            fl = g_any3B[row];
            mp = &g_maskB[row * 16];
        } else if (mode23) {
            fl = g_any3A[t];
            mp = &g_maskA[t * 16];
        }
        float* op = out + (size_t)row * VOCAB + vbase;
        if (!fl) {
            __stcs(reinterpret_cast<float4*>(op + tid * 4), r0);
            if (has2)
                __stcs(reinterpret_cast<float4*>(op + (tid + 256) * 4), r1);
        } else {
            unsigned mloc[16];
#pragma unroll
            for (int k = 0; k < 16; k++) mloc[k] = mp[k];
            {
                float4 o = r0;
                int v0 = vbase + tid * 4;
                o.x += mask_sum(mloc, Wout + (size_t)(v0 + 0) * HID);
                o.y += mask_sum(mloc, Wout + (size_t)(v0 + 1) * HID);
                o.z += mask_sum(mloc, Wout + (size_t)(v0 + 2) * HID);
                o.w += mask_sum(mloc, Wout + (size_t)(v0 + 3) * HID);
                __stcs(reinterpret_cast<float4*>(op + tid * 4), o);
            }
            if (has2) {
                float4 o = r1;
                int v0 = vbase + (tid + 256) * 4;
                o.x += mask_sum(mloc, Wout + (size_t)(v0 + 0) * HID);
                o.y += mask_sum(mloc, Wout + (size_t)(v0 + 1) * HID);
                o.z += mask_sum(mloc, Wout + (size_t)(v0 + 2) * HID);
                o.w += mask_sum(mloc, Wout + (size_t)(v0 + 3) * HID);
                __stcs(reinterpret_cast<float4*>(op + (tid + 256) * 4), o);
            }
        }
    }
}

// ===========================================================================
extern "C" void kernel_launch(void* const* d_in, const int* in_sizes, int n_in,
                              void* d_out, int out_size)
{
    const int*   x     = (const int*)  d_in[0];
    const float* emb   = (const float*)d_in[1];
    const float* pos   = (const float*)d_in[2];
    const float* beta1 = (const float*)d_in[3];
    const float* beta2 = (const float*)d_in[4];
    const float* beta3 = (const float*)d_in[5];
    const float* W2    = (const float*)d_in[6];
    const float* b2    = (const float*)d_in[7];
    const float* W3    = (const float*)d_in[8];
    const float* b3    = (const float*)d_in[9];
    const float* Wout  = (const float*)d_in[10];
    const float* bout  = (const float*)d_in[11];
    float* out = (float*)d_out;

    k1A_scan<<<NCHUNK * BATCH, 512>>>(x, emb, pos, beta1);
    k1B_combine<<<NCHUNK * BATCH + 1, 512>>>(beta1, beta2, beta3, b2, W3, b3);
    k2_fallback<<<BATCH, 32>>>(x, emb, pos, beta1, beta2, beta3, W2, b2, W3, b3);
    k3_logits<<<2048, 256>>>(Wout, bout, out);
}

// round 4
// speedup vs baseline: 1.3029x; 1.1921x over previous
#include <cuda_runtime.h>
#include <cuda_bf16.h>
#include <cstdint>

#define T_STEPS 512
#define BATCH   8
#define HID     512
#define VOCAB   32000
#define CHUNK   32                      // t-steps per scan chunk
#define NCHUNK  (T_STEPS / CHUNK)       // 16

// ---------------- device-global scratch (rewritten every replay) ------------
__device__ float    g_carry[NCHUNK * BATCH * HID];   // chunk-final local sums
__device__ float    g_locmax[NCHUNK * BATCH * HID];  // max local within chunk
__device__ int      g_dirtyB[BATCH];                // batch went through fallback
__device__ int      g_mode23;                       // 1 -> A-masks valid
__device__ unsigned g_any3A[T_STEPS];               // batch-independent spk3-any
__device__ unsigned g_maskA[T_STEPS * 16];
__device__ unsigned g_any3B[T_STEPS * BATCH];       // per-(t,b) fallback spk3
__device__ unsigned g_maskB[T_STEPS * BATCH * 16];

__device__ __forceinline__ float clip01(float b) { return fminf(fmaxf(b, 0.f), 1.f); }

// ===========================================================================
// K1A: blocks 0..255 : per-chunk reset-free layer-1 local scan.
//        c = bx>>4, b = (bx>>1)&7, half = bx&1; 256 threads -> h = half*256+tid
//        local_t = sum_{i<=t} beta^(t-i) u_i,  u = emb[x]+pos (gathered inline)
//        stores carry (local at chunk end) and locmax (max local in chunk).
//      block 256    : layers 2/3 closed-form bound (+ exact const-input sim
//                     with warp 0 if risky).
// ===========================================================================
__global__ void __launch_bounds__(256) k1A_scan(
    const int*   __restrict__ x,
    const float* __restrict__ emb,
    const float* __restrict__ pos,
    const float* __restrict__ beta1,
    const float* __restrict__ beta2,
    const float* __restrict__ beta3,
    const float* __restrict__ b2,
    const float* __restrict__ W3,
    const float* __restrict__ b3)
{
    const int tid = threadIdx.x;

    if (blockIdx.x < NCHUNK * BATCH * 2) {
        const int c    = blockIdx.x >> 4;
        const int b    = (blockIdx.x >> 1) & 7;
        const int half = blockIdx.x & 1;
        const int h    = half * 256 + tid;
        const int t0   = c * CHUNK;

        __shared__ unsigned xoff[CHUNK];
        if (tid < CHUNK) xoff[tid] = (unsigned)x[(t0 + tid) * BATCH + b] * (unsigned)HID;
        __syncthreads();

        const float bt = clip01(beta1[h]);
        float loc = 0.f, lmax = -1e30f;
#pragma unroll
        for (int i = 0; i < CHUNK; i++) {
            const float e = emb[(size_t)xoff[i] + h];
            const float p = pos[(size_t)(t0 + i) * HID + h];
            loc = bt * loc + (e + p);
            lmax = fmaxf(lmax, loc);
        }
        const size_t idx = (size_t)(c * BATCH + b) * HID + h;
        g_carry[idx]  = loc;
        g_locmax[idx] = lmax;
        return;
    }

    // ---- block 256: layers 2/3, batch-independent (valid when spk1 == 0) ----
    float lim = 0.f;
    for (int h = tid; h < HID; h += 256) {
        float be2 = clip01(beta2[h]);
        float c2  = fmaxf(b2[h], 0.f);
        float g2  = (be2 >= 1.f) ? (float)T_STEPS
                                 : (1.f - powf(be2, (float)T_STEPS)) / (1.f - be2);
        float be3 = clip01(beta3[h]);
        float c3  = fmaxf(b3[h], 0.f);
        float g3  = (be3 >= 1.f) ? (float)T_STEPS
                                 : (1.f - powf(be3, (float)T_STEPS)) / (1.f - be3);
        lim = fmaxf(lim, fmaxf(c2 * g2, c3 * g3));
    }
    int risky = __syncthreads_or(lim >= 0.98f);
    if (tid == 0) g_mode23 = risky;
    if (!risky || tid >= 32) return;

    // exact sequential sim of layers 2/3 with constant LIF2 input relu(b2)
    __shared__ float spkSh[HID];
    const int lane = tid;
    float m2[16], m3[16], s2[16], s3[16];
    float bb2[16], bb3[16], rb2[16], rb3[16], b3raw[16];
#pragma unroll
    for (int k = 0; k < 16; k++) {
        int h = lane + 32 * k;
        m2[k] = m3[k] = s2[k] = s3[k] = 0.f;
        bb2[k] = clip01(beta2[h]); bb3[k] = clip01(beta3[h]);
        rb2[k] = fmaxf(b2[h], 0.f);
        b3raw[k] = b3[h];
        rb3[k] = fmaxf(b3raw[k], 0.f);
    }
    for (int t = 0; t < T_STEPS; t++) {
        bool a = false;
#pragma unroll
        for (int k = 0; k < 16; k++) {
            m2[k] = bb2[k] * m2[k] + rb2[k] - s2[k];
            s2[k] = (m2[k] > 1.f) ? 1.f : 0.f;
            a = a || (s2[k] > 0.f);
        }
        unsigned a2 = __ballot_sync(0xffffffffu, a);
        float h3[16];
        if (a2) {
#pragma unroll
            for (int k = 0; k < 16; k++) spkSh[lane + 32 * k] = s2[k];
            __syncwarp();
#pragma unroll
            for (int k = 0; k < 16; k++) {
                int h = lane + 32 * k;
                float acc = b3raw[k];
                for (int j = 0; j < HID; j++)
                    if (spkSh[j] != 0.f) acc += W3[(size_t)h * HID + j];
                h3[k] = fmaxf(acc, 0.f);
            }
            __syncwarp();
        } else {
#pragma unroll
            for (int k = 0; k < 16; k++) h3[k] = rb3[k];
        }
        bool a3f = false;
#pragma unroll
        for (int k = 0; k < 16; k++) {
            m3[k] = bb3[k] * m3[k] + h3[k] - s3[k];
            s3[k] = (m3[k] > 1.f) ? 1.f : 0.f;
            a3f = a3f || (s3[k] > 0.f);
        }
        unsigned a3 = __ballot_sync(0xffffffffu, a3f);
        if (lane == 0) g_any3A[t] = a3 ? 1u : 0u;
        if (a3) {
#pragma unroll
            for (int k = 0; k < 16; k++) {
                unsigned mk = __ballot_sync(0xffffffffu, s3[k] != 0.f);
                if (lane == 0) g_maskA[t * 16 + k] = mk;
            }
        }
    }
}

// ===========================================================================
// K2: per-batch combine (upper-bound check over carries/locmax), then exact
//     full 3-layer sequential resim by warp 0 iff the bound was hit.
//     m_t within chunk c <= (M>0 ? bt*M : bt^32*M) + locmax_c   (bt in [0,1])
// ===========================================================================
__global__ void __launch_bounds__(512) k2_combine_fallback(
    const int*   __restrict__ x,
    const float* __restrict__ emb,
    const float* __restrict__ pos,
    const float* __restrict__ beta1,
    const float* __restrict__ beta2,
    const float* __restrict__ beta3,
    const float* __restrict__ W2,
    const float* __restrict__ b2,
    const float* __restrict__ W3,
    const float* __restrict__ b3)
{
    const int b   = blockIdx.x;
    const int tid = threadIdx.x;

    // ---- phase 1: combine ----
    bool any = false;
    {
        const int h = tid;
        const float bt = clip01(beta1[h]);
        float btL = bt;                        // beta^32 via 5 squarings
        btL = btL * btL; btL = btL * btL; btL = btL * btL;
        btL = btL * btL; btL = btL * btL;

        float M = 0.f;
#pragma unroll
        for (int c = 0; c < NCHUNK; c++) {
            const size_t idx = (size_t)(c * BATCH + b) * HID + h;
            const float lmax = g_locmax[idx];
            const float ub = ((M > 0.f) ? bt * M : btL * M) + lmax;
            any = any || (ub > 0.98f);
            M = btL * M + g_carry[idx];
        }
    }
    int flag = __syncthreads_or(any);
    if (tid == 0) g_dirtyB[b] = flag;
    if (!flag || tid >= 32) return;

    // ---- phase 2: exact full resim (warp 0 only; normally never taken) ----
    __shared__ float spkSh[HID];
    const int lane = tid;
    float m1[16], m2[16], m3[16], s1[16], s2[16], s3[16];
    float bt1[16], bt2[16], bt3[16], b2r[16], b3r[16];
#pragma unroll
    for (int k = 0; k < 16; k++) {
        int h = lane + 32 * k;
        m1[k] = m2[k] = m3[k] = 0.f;
        s1[k] = s2[k] = s3[k] = 0.f;
        bt1[k] = clip01(beta1[h]); bt2[k] = clip01(beta2[h]); bt3[k] = clip01(beta3[h]);
        b2r[k] = b2[h]; b3r[k] = b3[h];
    }
    for (int t = 0; t < T_STEPS; t++) {
        const int xv = x[t * BATCH + b];
        const float* ep = emb + (size_t)xv * HID;
        const float* pp = pos + (size_t)t * HID;
        bool a = false;
#pragma unroll
        for (int k = 0; k < 16; k++) {
            int h = lane + 32 * k;
            m1[k] = bt1[k] * m1[k] + (ep[h] + pp[h]) - s1[k];
            s1[k] = (m1[k] > 1.f) ? 1.f : 0.f;
            a = a || (s1[k] > 0.f);
        }
        unsigned a1 = __ballot_sync(0xffffffffu, a);
        float h2[16];
        if (a1) {
#pragma unroll
            for (int k = 0; k < 16; k++) spkSh[lane + 32 * k] = s1[k];
            __syncwarp();
#pragma unroll
            for (int k = 0; k < 16; k++) {
                int h = lane + 32 * k;
                float acc = b2r[k];
                for (int j = 0; j < HID; j++)
                    if (spkSh[j] != 0.f) acc += W2[(size_t)h * HID + j];
                h2[k] = fmaxf(acc, 0.f);
            }
            __syncwarp();
        } else {
#pragma unroll
            for (int k = 0; k < 16; k++) h2[k] = fmaxf(b2r[k], 0.f);
        }
        a = false;
#pragma unroll
        for (int k = 0; k < 16; k++) {
            m2[k] = bt2[k] * m2[k] + h2[k] - s2[k];
            s2[k] = (m2[k] > 1.f) ? 1.f : 0.f;
            a = a || (s2[k] > 0.f);
        }
        unsigned a2 = __ballot_sync(0xffffffffu, a);
        float h3[16];
        if (a2) {
#pragma unroll
            for (int k = 0; k < 16; k++) spkSh[lane + 32 * k] = s2[k];
            __syncwarp();
#pragma unroll
            for (int k = 0; k < 16; k++) {
                int h = lane + 32 * k;
                float acc = b3r[k];
                for (int j = 0; j < HID; j++)
                    if (spkSh[j] != 0.f) acc += W3[(size_t)h * HID + j];
                h3[k] = fmaxf(acc, 0.f);
            }
            __syncwarp();
        } else {
#pragma unroll
            for (int k = 0; k < 16; k++) h3[k] = fmaxf(b3r[k], 0.f);
        }
        a = false;
#pragma unroll
        for (int k = 0; k < 16; k++) {
            m3[k] = bt3[k] * m3[k] + h3[k] - s3[k];
            s3[k] = (m3[k] > 1.f) ? 1.f : 0.f;
            a = a || (s3[k] > 0.f);
        }
        unsigned a3 = __ballot_sync(0xffffffffu, a);
        int row = t * BATCH + b;
        if (lane == 0) g_any3B[row] = a3 ? 1u : 0u;
        if (a3) {
#pragma unroll
            for (int k = 0; k < 16; k++) {
                unsigned mk = __ballot_sync(0xffffffffu, s3[k] != 0.f);
                if (lane == 0) g_maskB[row * 16 + k] = mk;
            }
        }
    }
}

// ===========================================================================
// K3: logits. Fast path: out[row] = bout (registers -> streaming float4 stores).
//     Slow path (row flagged): out[v] = bout[v] + sum over set h of Wout[v][h].
// ===========================================================================
__device__ __forceinline__ float mask_sum(const unsigned* __restrict__ mp,
                                          const float* __restrict__ wrow)
{
    float a = 0.f;
#pragma unroll
    for (int k = 0; k < 16; k++) {
        unsigned m = mp[k];
        while (m) {
            int j = __ffs(m) - 1;
            m &= m - 1;
            a += wrow[32 * k + j];
        }
    }
    return a;
}

__global__ void __launch_bounds__(256) k3_logits(
    const float* __restrict__ Wout,
    const float* __restrict__ bout,
    float*       __restrict__ out)
{
    const int tid   = threadIdx.x;
    const int c     = blockIdx.x & 15;        // vocab chunk
    const int g     = blockIdx.x >> 4;        // row group
    const int vbase = c * 2000;
    const bool has2 = (tid + 256) < 500;      // 500 float4 per chunk

    float4 r0 = *reinterpret_cast<const float4*>(bout + vbase + tid * 4);
    float4 r1 = make_float4(0.f, 0.f, 0.f, 0.f);
    if (has2) r1 = *reinterpret_cast<const float4*>(bout + vbase + (tid + 256) * 4);

    const int mode23 = g_mode23;
    int dirty[BATCH];
#pragma unroll
    for (int b = 0; b < BATCH; b++) dirty[b] = g_dirtyB[b];

    const int row0 = g * 32;
    for (int r = 0; r < 32; r++) {
        const int row = row0 + r;
        const int t = row >> 3;
        const int b = row & 7;
        unsigned fl = 0;
        const unsigned* mp = nullptr;
        if (dirty[b]) {
            fl = g_any3B[row];
            mp = &g_maskB[row * 16];
        } else if (mode23) {
            fl = g_any3A[t];
            mp = &g_maskA[t * 16];
        }
        float* op = out + (size_t)row * VOCAB + vbase;
        if (!fl) {
            __stcs(reinterpret_cast<float4*>(op + tid * 4), r0);
            if (has2)
                __stcs(reinterpret_cast<float4*>(op + (tid + 256) * 4), r1);
        } else {
            unsigned mloc[16];
#pragma unroll
            for (int k = 0; k < 16; k++) mloc[k] = mp[k];
            {
                float4 o = r0;
                int v0 = vbase + tid * 4;
                o.x += mask_sum(mloc, Wout + (size_t)(v0 + 0) * HID);
                o.y += mask_sum(mloc, Wout + (size_t)(v0 + 1) * HID);
                o.z += mask_sum(mloc, Wout + (size_t)(v0 + 2) * HID);
                o.w += mask_sum(mloc, Wout + (size_t)(v0 + 3) * HID);
                __stcs(reinterpret_cast<float4*>(op + tid * 4), o);
            }
            if (has2) {
                float4 o = r1;
                int v0 = vbase + (tid + 256) * 4;
                o.x += mask_sum(mloc, Wout + (size_t)(v0 + 0) * HID);
                o.y += mask_sum(mloc, Wout + (size_t)(v0 + 1) * HID);
                o.z += mask_sum(mloc, Wout + (size_t)(v0 + 2) * HID);
                o.w += mask_sum(mloc, Wout + (size_t)(v0 + 3) * HID);
                __stcs(reinterpret_cast<float4*>(op + (tid + 256) * 4), o);
            }
        }
    }
}

// ===========================================================================
extern "C" void kernel_launch(void* const* d_in, const int* in_sizes, int n_in,
                              void* d_out, int out_size)
{
    const int*   x     = (const int*)  d_in[0];
    const float* emb   = (const float*)d_in[1];
    const float* pos   = (const float*)d_in[2];
    const float* beta1 = (const float*)d_in[3];
    const float* beta2 = (const float*)d_in[4];
    const float* beta3 = (const float*)d_in[5];
    const float* W2    = (const float*)d_in[6];
    const float* b2    = (const float*)d_in[7];
    const float* W3    = (const float*)d_in[8];
    const float* b3    = (const float*)d_in[9];
    const float* Wout  = (const float*)d_in[10];
    const float* bout  = (const float*)d_in[11];
    float* out = (float*)d_out;

    k1A_scan<<<NCHUNK * BATCH * 2 + 1, 256>>>(x, emb, pos, beta1, beta2, beta3,
                                              b2, W3, b3);
    k2_combine_fallback<<<BATCH, 512>>>(x, emb, pos, beta1, beta2, beta3,
                                        W2, b2, W3, b3);
    k3_logits<<<2048, 256>>>(Wout, bout, out);
}